// round 15
// baseline (speedup 1.0000x reference)
#include <cuda_runtime.h>
#include <cuda_fp16.h>
#include <stdint.h>
#include <math.h>

#define D 768
#define BATCH 2
#define SEQ 2048
#define NROWS (BATCH*SEQ)   // 4096
#define NHEADS 12
#define HDIM 64
#define EPS 1e-5f

#define BK 32
#define KSTAGES (D/BK)      // 24

// softmax scale folded into Q and bias: logits computed in log2 domain
#define QSCALE 0.1803368801111204f   // 0.125 * log2(e)

#define NSPLIT 2
#define KT_PER_SPLIT (SEQ/64/NSPLIT) // 16

// ---------------- scratch ----------------
__device__ float g_xmid[NROWS*D];
__device__ __half g_xn16[NROWS*D];
__device__ __half g_q16[NROWS*D], g_k16[NROWS*D], g_v16[NROWS*D];
__device__ __half g_a16[NROWS*D];
__device__ __half g_h16[NROWS*D];
__device__ __half g_wt16[6*D*D];
__device__ unsigned char g_mask8[(size_t)BATCH*SEQ*SEQ];
__device__ float g_po[NSPLIT][NROWS*D];          // unnormalized O partials
__device__ float g_pl[NSPLIT][NROWS*NHEADS];     // lsum partials
__device__ float g_pm[NSPLIT][NROWS*NHEADS];     // running max partials (log2)

// ---------------- PTX helpers ----------------
__device__ __forceinline__ uint32_t smem_u32(const void* p) {
    uint32_t a;
    asm("{ .reg .u64 t; cvta.to.shared.u64 t, %1; cvt.u32.u64 %0, t; }" : "=r"(a) : "l"(p));
    return a;
}
__device__ __forceinline__ void cp_async16(uint32_t dst, const void* src) {
    asm volatile("cp.async.ca.shared.global [%0], [%1], 16;\n" :: "r"(dst), "l"(src));
}
__device__ __forceinline__ void cp_commit() { asm volatile("cp.async.commit_group;\n"); }
__device__ __forceinline__ void cp_wait0()  { asm volatile("cp.async.wait_group 0;\n" ::: "memory"); }
__device__ __forceinline__ void cp_wait1()  { asm volatile("cp.async.wait_group 1;\n" ::: "memory"); }

__device__ __forceinline__ void ldsm_x4(uint32_t addr, uint32_t* r) {
    asm volatile("ldmatrix.sync.aligned.m8n8.x4.shared.b16 {%0,%1,%2,%3}, [%4];"
                 : "=r"(r[0]), "=r"(r[1]), "=r"(r[2]), "=r"(r[3]) : "r"(addr));
}
__device__ __forceinline__ void ldsm_x4t(uint32_t addr, uint32_t* r) {
    asm volatile("ldmatrix.sync.aligned.m8n8.x4.trans.shared.b16 {%0,%1,%2,%3}, [%4];"
                 : "=r"(r[0]), "=r"(r[1]), "=r"(r[2]), "=r"(r[3]) : "r"(addr));
}
__device__ __forceinline__ void mma_f16(float* c, const uint32_t* a, uint32_t b0, uint32_t b1) {
    asm volatile("mma.sync.aligned.m16n8k16.row.col.f32.f16.f16.f32 "
                 "{%0,%1,%2,%3},{%4,%5,%6,%7},{%8,%9},{%0,%1,%2,%3};"
                 : "+f"(c[0]), "+f"(c[1]), "+f"(c[2]), "+f"(c[3])
                 : "r"(a[0]), "r"(a[1]), "r"(a[2]), "r"(a[3]), "r"(b0), "r"(b1));
}

__device__ __forceinline__ uint32_t pack_half2(float a, float b) {
    __half2 h = __floats2half2_rn(a, b);
    return *(uint32_t*)&h;
}

// ---------------- weight transpose -> fp16 (all 6 in one launch) ----------------
__global__ void transpose6(const float* __restrict__ w0, const float* __restrict__ w1,
                           const float* __restrict__ w2, const float* __restrict__ w3,
                           const float* __restrict__ w4, const float* __restrict__ w5,
                           __half* __restrict__ T16) {
    __shared__ float tile[32][33];
    int z = blockIdx.z;
    const float* W = (z == 0) ? w0 : (z == 1) ? w1 : (z == 2) ? w2
                   : (z == 3) ? w3 : (z == 4) ? w4 : w5;
    __half* t16 = T16 + (size_t)z * D * D;
    int bx = blockIdx.x * 32, by = blockIdx.y * 32;
    int tx = threadIdx.x, ty = threadIdx.y;
    #pragma unroll
    for (int i = 0; i < 4; i++)
        tile[ty + 8*i][tx] = W[(size_t)(by + ty + 8*i) * D + bx + tx];
    __syncthreads();
    #pragma unroll
    for (int i = 0; i < 4; i++) {
        float v = tile[tx][ty + 8*i];
        t16[(size_t)(bx + ty + 8*i) * D + by + tx] = __float2half(v);
    }
}

// ---------------- mask int32 -> int8 ----------------
__global__ void mask_pack(const int* __restrict__ m, unsigned char* __restrict__ m8, int n4) {
    int i = blockIdx.x * blockDim.x + threadIdx.x;
    if (i < n4) {
        int4 v = *(const int4*)(m + (size_t)i * 4);
        uchar4 o;
        o.x = (unsigned char)v.x; o.y = (unsigned char)v.y;
        o.z = (unsigned char)v.z; o.w = (unsigned char)v.w;
        *(uchar4*)(m8 + (size_t)i * 4) = o;
    }
}

// ---------------- LayerNorm -> fp16 ----------------
__global__ void ln_f16(const float* __restrict__ x, const float* __restrict__ w,
                       const float* __restrict__ b, __half* __restrict__ y16) {
    __shared__ float sh_s[8], sh_ss[8];
    __shared__ float mu_sh, rstd_sh;
    int row = blockIdx.x;
    const float* xr = x + (size_t)row * D;
    int t = threadIdx.x;
    float v0 = xr[t], v1 = xr[t + 256], v2 = xr[t + 512];
    float s  = v0 + v1 + v2;
    float ss = v0*v0 + v1*v1 + v2*v2;
    #pragma unroll
    for (int o = 16; o > 0; o >>= 1) {
        s  += __shfl_xor_sync(0xffffffffu, s,  o);
        ss += __shfl_xor_sync(0xffffffffu, ss, o);
    }
    int wid = t >> 5, lane = t & 31;
    if (lane == 0) { sh_s[wid] = s; sh_ss[wid] = ss; }
    __syncthreads();
    if (t == 0) {
        float S = 0.f, SS = 0.f;
        #pragma unroll
        for (int i = 0; i < 8; i++) { S += sh_s[i]; SS += sh_ss[i]; }
        float mu = S / (float)D;
        float var = SS / (float)D - mu * mu;
        mu_sh = mu; rstd_sh = rsqrtf(var + EPS);
    }
    __syncthreads();
    float mu = mu_sh, rs = rstd_sh;
    size_t base = (size_t)row * D;
    #pragma unroll
    for (int i = 0; i < 3; i++) {
        int c = t + 256 * i;
        float v = (i == 0) ? v0 : (i == 1) ? v1 : v2;
        float o = (v - mu) * rs * w[c] + b[c];
        y16[base + c] = __float2half(o);
    }
}

// =============== fp16 HMMA GEMM core A: CTA 128x128 (for balanced big grids) =====
#define STG_A 16384
#define GSMEM_A (2*STG_A)

__device__ __forceinline__ void gemm128(
    const __half* __restrict__ A16, const __half* __restrict__ W16,
    const float* __restrict__ bias, float* __restrict__ Cf,
    __half* __restrict__ C16, int brow, int bcol, uint32_t sb, float oscale)
{
    int t = threadIdx.x;
    int wid = t >> 5, lane = t & 31;
    int wm = wid & 1, wn = wid >> 1;

    float acc[4][4][4];
    #pragma unroll
    for (int i = 0; i < 4; i++)
        #pragma unroll
        for (int j = 0; j < 4; j++)
            #pragma unroll
            for (int c = 0; c < 4; c++) acc[i][j][c] = 0.f;

    auto load_stage = [&](int s) {
        uint32_t base = sb + (uint32_t)((s & 1) * STG_A);
        int k0 = s * BK;
        #pragma unroll
        for (int i = 0; i < 2; i++) {
            int id = t + i * 256;
            int r = id >> 2, c = id & 3;
            uint32_t so = (uint32_t)(r * 64 + ((c ^ ((r >> 1) & 3)) * 16));
            cp_async16(base + so,        A16 + (size_t)(brow + r) * D + k0 + c * 8);
            cp_async16(base + 8192 + so, W16 + (size_t)(bcol + r) * D + k0 + c * 8);
        }
        cp_commit();
    };

    load_stage(0);

    for (int s = 0; s < KSTAGES; s++) {
        if (s < KSTAGES - 1) load_stage(s + 1);
        if (s < KSTAGES - 1) cp_wait1(); else cp_wait0();
        __syncthreads();

        uint32_t base = sb + (uint32_t)((s & 1) * STG_A);
        #pragma unroll
        for (int kstep = 0; kstep < 2; kstep++) {
            uint32_t af[4][4];
            #pragma unroll
            for (int mt = 0; mt < 4; mt++) {
                int row = wm * 64 + mt * 16 + (lane & 15);
                int chunk = kstep * 2 + (lane >> 4);
                uint32_t so = (uint32_t)(row * 64 + ((chunk ^ ((row >> 1) & 3)) * 16));
                ldsm_x4(base + so, af[mt]);
            }
            uint32_t bf[2][4];
            #pragma unroll
            for (int nt2 = 0; nt2 < 2; nt2++) {
                int row = wn * 32 + nt2 * 16 + (lane & 7) + ((lane & 16) ? 8 : 0);
                int chunk = kstep * 2 + ((lane >> 3) & 1);
                uint32_t so = (uint32_t)(row * 64 + ((chunk ^ ((row >> 1) & 3)) * 16));
                ldsm_x4(base + 8192 + so, bf[nt2]);
            }
            #pragma unroll
            for (int mt = 0; mt < 4; mt++)
                #pragma unroll
                for (int nt = 0; nt < 4; nt++)
                    mma_f16(acc[mt][nt], af[mt],
                            bf[nt >> 1][(nt & 1) * 2], bf[nt >> 1][(nt & 1) * 2 + 1]);
        }
        __syncthreads();
    }

    #pragma unroll
    for (int mt = 0; mt < 4; mt++) {
        #pragma unroll
        for (int nt = 0; nt < 4; nt++) {
            float* c = acc[mt][nt];
            int col = bcol + wn * 32 + nt * 8 + (lane & 3) * 2;
            #pragma unroll
            for (int half = 0; half < 2; half++) {
                int row = brow + wm * 64 + mt * 16 + (lane >> 2) + half * 8;
                float2 o;
                o.x = c[half * 2 + 0];
                o.y = c[half * 2 + 1];
                const float2 bb = *(const float2*)(bias + col);
                o.x = (o.x + bb.x) * oscale;
                o.y = (o.y + bb.y) * oscale;
                size_t gidx = (size_t)row * D + col;
                if (Cf)  *(float2*)(Cf + gidx) = o;
                if (C16) *(uint32_t*)(C16 + gidx) = pack_half2(o.x, o.y);
            }
        }
    }
}

// Merged QKV: grid (18, 32); sel = x/6, col tile = x%6. Q pre-scaled by QSCALE.
__global__ void __launch_bounds__(256, 2)
qkv_gemm(const __half* __restrict__ A16, const __half* __restrict__ Wt16,
         const float* __restrict__ bq, const float* __restrict__ bk, const float* __restrict__ bv,
         __half* __restrict__ q16, __half* __restrict__ k16, __half* __restrict__ v16)
{
    extern __shared__ char smem[];
    int sel = blockIdx.x / 6;
    int bcol = (blockIdx.x % 6) * 128;
    const __half* W = Wt16 + (size_t)sel * D * D;
    const float* bias = (sel == 0) ? bq : (sel == 1) ? bk : bv;
    __half* C16 = (sel == 0) ? q16 : (sel == 1) ? k16 : v16;
    float oscale = (sel == 0) ? QSCALE : 1.0f;
    gemm128(A16, W, bias, nullptr, C16, blockIdx.y * 128, bcol, smem_u32(smem), oscale);
}

// =============== fp16 HMMA GEMM core B: CTA 128x64, 3 CTAs/SM (serial GEMMs) =====
#define STG_B 12288
#define GSMEM_B (2*STG_B)

__global__ void __launch_bounds__(256, 3)
hmma_gemm(const __half* __restrict__ A16, const __half* __restrict__ W16,
          const float* __restrict__ bias, const float* __restrict__ res,
          float* __restrict__ Cf, __half* __restrict__ C16, int relu)
{
    extern __shared__ char smem[];
    uint32_t sb = smem_u32(smem);
    int t = threadIdx.x;
    int wid = t >> 5, lane = t & 31;
    int wm = wid & 3, wn = wid >> 2;
    int brow = blockIdx.y * 128, bcol = blockIdx.x * 64;

    float acc[2][4][4];
    #pragma unroll
    for (int i = 0; i < 2; i++)
        #pragma unroll
        for (int j = 0; j < 4; j++)
            #pragma unroll
            for (int c = 0; c < 4; c++) acc[i][j][c] = 0.f;

    auto load_stage = [&](int s) {
        uint32_t base = sb + (uint32_t)((s & 1) * STG_B);
        int k0 = s * BK;
        #pragma unroll
        for (int i = 0; i < 2; i++) {
            int id = t + i * 256;
            int r = id >> 2, c = id & 3;
            uint32_t so = (uint32_t)(r * 64 + ((c ^ ((r >> 1) & 3)) * 16));
            cp_async16(base + so, A16 + (size_t)(brow + r) * D + k0 + c * 8);
        }
        {
            int r = t >> 2, c = t & 3;
            uint32_t so = (uint32_t)(r * 64 + ((c ^ ((r >> 1) & 3)) * 16));
            cp_async16(base + 8192 + so, W16 + (size_t)(bcol + r) * D + k0 + c * 8);
        }
        cp_commit();
    };

    load_stage(0);

    for (int s = 0; s < KSTAGES; s++) {
        if (s < KSTAGES - 1) load_stage(s + 1);
        if (s < KSTAGES - 1) cp_wait1(); else cp_wait0();
        __syncthreads();

        uint32_t base = sb + (uint32_t)((s & 1) * STG_B);
        #pragma unroll
        for (int kstep = 0; kstep < 2; kstep++) {
            uint32_t af[2][4];
            #pragma unroll
            for (int mt = 0; mt < 2; mt++) {
                int row = wm * 32 + mt * 16 + (lane & 15);
                int chunk = kstep * 2 + (lane >> 4);
                uint32_t so = (uint32_t)(row * 64 + ((chunk ^ ((row >> 1) & 3)) * 16));
                ldsm_x4(base + so, af[mt]);
            }
            uint32_t bf[2][4];
            #pragma unroll
            for (int nt2 = 0; nt2 < 2; nt2++) {
                int row = wn * 32 + nt2 * 16 + (lane & 7) + ((lane & 16) ? 8 : 0);
                int chunk = kstep * 2 + ((lane >> 3) & 1);
                uint32_t so = (uint32_t)(row * 64 + ((chunk ^ ((row >> 1) & 3)) * 16));
                ldsm_x4(base + 8192 + so, bf[nt2]);
            }
            #pragma unroll
            for (int mt = 0; mt < 2; mt++)
                #pragma unroll
                for (int nt = 0; nt < 4; nt++)
                    mma_f16(acc[mt][nt], af[mt],
                            bf[nt >> 1][(nt & 1) * 2], bf[nt >> 1][(nt & 1) * 2 + 1]);
        }
        __syncthreads();
    }

    #pragma unroll
    for (int mt = 0; mt < 2; mt++) {
        #pragma unroll
        for (int nt = 0; nt < 4; nt++) {
            float* c = acc[mt][nt];
            int col = bcol + wn * 32 + nt * 8 + (lane & 3) * 2;
            #pragma unroll
            for (int half = 0; half < 2; half++) {
                int row = brow + wm * 32 + mt * 16 + (lane >> 2) + half * 8;
                float2 o;
                o.x = c[half * 2 + 0];
                o.y = c[half * 2 + 1];
                const float2 bb = *(const float2*)(bias + col);
                o.x += bb.x; o.y += bb.y;
                size_t gidx = (size_t)row * D + col;
                if (res) {
                    float2 rv = *(const float2*)(res + gidx);
                    o.x += rv.x; o.y += rv.y;
                }
                if (relu) { o.x = fmaxf(o.x, 0.f); o.y = fmaxf(o.y, 0.f); }
                if (Cf)  *(float2*)(Cf + gidx) = o;
                if (C16) *(uint32_t*)(C16 + gidx) = pack_half2(o.x, o.y);
            }
        }
    }
}

// ---------------- fp16 flash attention, split-KV (log2-domain softmax) -----------
#define AOFF_Q    0
#define AOFF_KV   16384              // + buf*16384 : K(8K) V(8K)
#define AOFF_BIAS 49152              // 128 rows x 272B
#define AOFF_MASK 83968              // 128 rows x 80B
#define ASMEM     94208

__global__ void __launch_bounds__(256, 2)
attn_mma(const __half* __restrict__ q16, const __half* __restrict__ k16,
         const __half* __restrict__ v16,
         const float* __restrict__ bias, const unsigned char* __restrict__ mask8,
         float* __restrict__ po, float* __restrict__ pl, float* __restrict__ pm)
{
    extern __shared__ char smem[];
    uint32_t sb = smem_u32(smem);
    int t = threadIdx.x;
    int w = t >> 5, lane = t & 31;

    int qt = blockIdx.x;
    int hb = blockIdx.y;
    int split = blockIdx.z;
    int hd = hb >> 1;
    int b  = hb & 1;
    const int kt0 = split * KT_PER_SPLIT;
    const int ktend = kt0 + KT_PER_SPLIT;

    float* po_s = po + (size_t)split * NROWS * D;
    float* pl_s = pl + (size_t)split * NROWS * NHEADS;
    float* pm_s = pm + (size_t)split * NROWS * NHEADS;

    size_t qrow0 = (size_t)b * SEQ + qt * 128;
    const __half* qg = q16 + qrow0 * D + hd * HDIM;
    const __half* kg = k16 + (size_t)b * SEQ * D + hd * HDIM;
    const __half* vg = v16 + (size_t)b * SEQ * D + hd * HDIM;
    const float* biasbase = bias + ((size_t)(hd * BATCH + b) * SEQ + qt * 128) * SEQ;
    const unsigned char* maskbase = mask8 + ((size_t)b * SEQ + qt * 128) * SEQ;

    #pragma unroll
    for (int i = 0; i < 4; i++) {
        int id = t + i * 256;
        int row = id >> 3, c = id & 7;
        uint32_t so = (uint32_t)(row * 128 + ((c ^ (row & 7)) * 16));
        cp_async16(sb + AOFF_Q + so, qg + (size_t)row * D + c * 8);
    }
    cp_commit();

    auto load_kv = [&](int kt) {
        uint32_t base = sb + AOFF_KV + (uint32_t)((kt & 1) * 16384);
        #pragma unroll
        for (int i = 0; i < 2; i++) {
            int id = t + i * 256;
            int row = id >> 3, c = id & 7;
            uint32_t so = (uint32_t)(row * 128 + ((c ^ (row & 7)) * 16));
            size_t g = (size_t)(kt * 64 + row) * D + c * 8;
            cp_async16(base + so,        kg + g);
            cp_async16(base + 8192 + so, vg + g);
        }
        cp_commit();
    };

    auto load_bm = [&](int kt) {
        #pragma unroll
        for (int i = 0; i < 8; i++) {
            int id = t + i * 256;
            int row = id >> 4, c = id & 15;
            cp_async16(sb + AOFF_BIAS + (uint32_t)(row * 272 + c * 16),
                       biasbase + (size_t)row * SEQ + kt * 64 + c * 4);
        }
        #pragma unroll
        for (int i = 0; i < 2; i++) {
            int id = t + i * 256;
            int row = id >> 2, c = id & 3;
            cp_async16(sb + AOFF_MASK + (uint32_t)(row * 80 + c * 16),
                       maskbase + (size_t)row * SEQ + kt * 64 + c * 16);
        }
        cp_commit();
    };

    load_kv(kt0);
    load_bm(kt0);
    load_kv(kt0 + 1);

    float accO[8][4];
    #pragma unroll
    for (int j = 0; j < 8; j++)
        #pragma unroll
        for (int c = 0; c < 4; c++) accO[j][c] = 0.f;
    float m[2] = {-1e30f, -1e30f}, lsum[2] = {0.f, 0.f};

    for (int kt = kt0; kt < ktend; kt++) {
        if (kt < ktend - 1) cp_wait1(); else cp_wait0();
        __syncthreads();

        uint32_t base = sb + AOFF_KV + (uint32_t)((kt & 1) * 16384);

        // ---- S = Q @ K^T  (Q pre-scaled; S in log2 domain) ----
        float s[8][4];
        #pragma unroll
        for (int j = 0; j < 8; j++)
            #pragma unroll
            for (int c = 0; c < 4; c++) s[j][c] = 0.f;

        #pragma unroll
        for (int kk = 0; kk < 4; kk++) {
            uint32_t qa[4];
            {
                int row = w * 16 + (lane & 15);
                int ch = kk * 2 + (lane >> 4);
                uint32_t so = (uint32_t)(row * 128 + ((ch ^ (row & 7)) * 16));
                ldsm_x4(sb + AOFF_Q + so, qa);
            }
            uint32_t kb[4][4];
            #pragma unroll
            for (int np = 0; np < 4; np++) {
                int row = np * 16 + (lane & 7) + ((lane & 16) ? 8 : 0);
                int ch = kk * 2 + ((lane >> 3) & 1);
                uint32_t so = (uint32_t)(row * 128 + ((ch ^ (row & 7)) * 16));
                ldsm_x4(base + so, kb[np]);
            }
            #pragma unroll
            for (int j = 0; j < 8; j++)
                mma_f16(s[j], qa, kb[j >> 1][(j & 1) * 2], kb[j >> 1][(j & 1) * 2 + 1]);
        }

        // ---- softmax in log2 domain ----
        #pragma unroll
        for (int hh = 0; hh < 2; hh++) {
            int row = w * 16 + (lane >> 2) + hh * 8;
            const float* bsm = (const float*)(smem + AOFF_BIAS + (size_t)row * 272)
                               + (lane & 3) * 2;
            const unsigned char* msm = (const unsigned char*)(smem + AOFF_MASK
                               + (size_t)row * 80) + (lane & 3) * 2;
            float mx = -1e30f;
            #pragma unroll
            for (int j = 0; j < 8; j++) {
                float2 bb = *(const float2*)(bsm + j * 8);
                uchar2 mm = *(const uchar2*)(msm + j * 8);
                float v0 = mm.x ? fmaf(bb.x, QSCALE, s[j][hh*2+0]) : -1e30f;
                float v1 = mm.y ? fmaf(bb.y, QSCALE, s[j][hh*2+1]) : -1e30f;
                s[j][hh*2+0] = v0; s[j][hh*2+1] = v1;
                mx = fmaxf(mx, fmaxf(v0, v1));
            }
            mx = fmaxf(mx, __shfl_xor_sync(0xffffffffu, mx, 1));
            mx = fmaxf(mx, __shfl_xor_sync(0xffffffffu, mx, 2));
            float mn = fmaxf(m[hh], mx);
            float alpha = exp2f(m[hh] - mn);
            m[hh] = mn;
            float rs = 0.f;
            #pragma unroll
            for (int j = 0; j < 8; j++) {
                float e0 = exp2f(s[j][hh*2+0] - mn);
                float e1 = exp2f(s[j][hh*2+1] - mn);
                s[j][hh*2+0] = e0; s[j][hh*2+1] = e1;
                rs += e0 + e1;
            }
            rs += __shfl_xor_sync(0xffffffffu, rs, 1);
            rs += __shfl_xor_sync(0xffffffffu, rs, 2);
            lsum[hh] = lsum[hh] * alpha + rs;
            #pragma unroll
            for (int j = 0; j < 8; j++) {
                accO[j][hh*2+0] *= alpha;
                accO[j][hh*2+1] *= alpha;
            }
        }

        // ---- O += P @ V ----
        #pragma unroll
        for (int kk = 0; kk < 4; kk++) {
            int j0 = kk * 2, j1 = kk * 2 + 1;
            uint32_t pa[4];
            pa[0] = pack_half2(s[j0][0], s[j0][1]);
            pa[1] = pack_half2(s[j0][2], s[j0][3]);
            pa[2] = pack_half2(s[j1][0], s[j1][1]);
            pa[3] = pack_half2(s[j1][2], s[j1][3]);
            uint32_t vb[4][4];
            #pragma unroll
            for (int np = 0; np < 4; np++) {
                int i = lane >> 3, jj = lane & 7;
                int tok = kk * 16 + (i & 1) * 8 + jj;
                int ch = np * 2 + (i >> 1);
                uint32_t so = (uint32_t)(tok * 128 + ((ch ^ (tok & 7)) * 16));
                ldsm_x4t(base + 8192 + so, vb[np]);
            }
            #pragma unroll
            for (int j = 0; j < 8; j++)
                mma_f16(accO[j], pa, vb[j >> 1][(j & 1) * 2], vb[j >> 1][(j & 1) * 2 + 1]);
        }
        __syncthreads();

        if (kt + 1 < ktend) load_bm(kt + 1);
        if (kt + 2 < ktend) load_kv(kt + 2);
    }

    // ---- epilogue: write unnormalized partials ----
    #pragma unroll
    for (int hh = 0; hh < 2; hh++) {
        size_t row = qrow0 + w * 16 + (lane >> 2) + hh * 8;
        #pragma unroll
        for (int j = 0; j < 8; j++) {
            int col = hd * HDIM + j * 8 + (lane & 3) * 2;
            float2 o; o.x = accO[j][hh*2+0]; o.y = accO[j][hh*2+1];
            *(float2*)(po_s + row * D + col) = o;
        }
        if ((lane & 3) == 0) {
            pl_s[row * NHEADS + hd] = lsum[hh];
            pm_s[row * NHEADS + hd] = m[hh];
        }
    }
}

// ---------------- combine split-KV partials -> fp16 attention out ----------------
__global__ void attn_combine(const float* __restrict__ po, const float* __restrict__ pl,
                             const float* __restrict__ pm, __half* __restrict__ out16) {
    size_t i = (size_t)blockIdx.x * 256 + threadIdx.x;   // over NROWS*D/2 (float2 units)
    size_t e = i * 2;
    size_t row = e / D;
    int col = (int)(e % D);
    int hd = col >> 6;
    size_t lmi = row * NHEADS + hd;
    float m0 = pm[lmi], m1 = pm[NROWS * NHEADS + lmi];
    float l0 = pl[lmi], l1 = pl[NROWS * NHEADS + lmi];
    float mm = fmaxf(m0, m1);
    float a0 = exp2f(m0 - mm), a1 = exp2f(m1 - mm);
    float inv = 1.0f / (l0 * a0 + l1 * a1);
    float2 o0 = *(const float2*)(po + e);
    float2 o1 = *(const float2*)(po + (size_t)NROWS * D + e);
    float v0 = (o0.x * a0 + o1.x * a1) * inv;
    float v1 = (o0.y * a0 + o1.y * a1) * inv;
    *(uint32_t*)(out16 + e) = pack_half2(v0, v1);
}

// ---------------- host launcher --------------------------------------------------
extern "C" void kernel_launch(void* const* d_in, const int* in_sizes, int n_in,
                              void* d_out, int out_size) {
    const float* x     = (const float*)d_in[0];
    const float* bias  = (const float*)d_in[1];
    const int*   mask  = (const int*)d_in[2];
    const float* ln1_w = (const float*)d_in[3];
    const float* ln1_b = (const float*)d_in[4];
    const float* wq    = (const float*)d_in[5];
    const float* bq    = (const float*)d_in[6];
    const float* wk    = (const float*)d_in[7];
    const float* bk    = (const float*)d_in[8];
    const float* wv    = (const float*)d_in[9];
    const float* bv    = (const float*)d_in[10];
    const float* wo    = (const float*)d_in[11];
    const float* bo    = (const float*)d_in[12];
    const float* ln2_w = (const float*)d_in[13];
    const float* ln2_b = (const float*)d_in[14];
    const float* w1    = (const float*)d_in[15];
    const float* b1    = (const float*)d_in[16];
    const float* w2    = (const float*)d_in[17];
    const float* b2    = (const float*)d_in[18];
    float* out = (float*)d_out;

    float *xmid, *po, *pl, *pm;
    __half *xn16, *q16, *k16, *v16, *a16, *h16, *wt16;
    unsigned char* mask8;
    cudaGetSymbolAddress((void**)&xmid, g_xmid);
    cudaGetSymbolAddress((void**)&xn16, g_xn16);
    cudaGetSymbolAddress((void**)&q16,  g_q16);
    cudaGetSymbolAddress((void**)&k16,  g_k16);
    cudaGetSymbolAddress((void**)&v16,  g_v16);
    cudaGetSymbolAddress((void**)&a16,  g_a16);
    cudaGetSymbolAddress((void**)&h16,  g_h16);
    cudaGetSymbolAddress((void**)&wt16, g_wt16);
    cudaGetSymbolAddress((void**)&mask8, g_mask8);
    cudaGetSymbolAddress((void**)&po,   g_po);
    cudaGetSymbolAddress((void**)&pl,   g_pl);
    cudaGetSymbolAddress((void**)&pm,   g_pm);

    cudaFuncSetAttribute(hmma_gemm, cudaFuncAttributeMaxDynamicSharedMemorySize, GSMEM_B);
    cudaFuncSetAttribute(qkv_gemm,  cudaFuncAttributeMaxDynamicSharedMemorySize, GSMEM_A);
    cudaFuncSetAttribute(attn_mma,  cudaFuncAttributeMaxDynamicSharedMemorySize, ASMEM);

    dim3 tgrid(24, 24, 6), tblk(32, 8);
    transpose6<<<tgrid, tblk>>>(wq, wk, wv, wo, w1, w2, wt16);
    mask_pack<<<(BATCH*SEQ*SEQ/4 + 255)/256, 256>>>(mask, mask8, BATCH*SEQ*SEQ/4);

    dim3 ggrid(D / 64, NROWS / 128);     // (12, 32) = 384
    dim3 qgrid(18, NROWS / 128);         // (18, 32) = 576

    // LN1 -> fp16
    ln_f16<<<NROWS, 256>>>(x, ln1_w, ln1_b, xn16);
    // merged QKV projections (128x128 tiles; Q pre-scaled)
    qkv_gemm<<<qgrid, 256, GSMEM_A>>>(xn16, wt16, bq, bk, bv, q16, k16, v16);
    // attention: split-KV over grid.z = 2, then combine
    dim3 attn_grid(SEQ / 128, NHEADS * BATCH, NSPLIT);  // (16, 24, 2) = 768
    attn_mma<<<attn_grid, 256, ASMEM>>>(q16, k16, v16, bias, mask8, po, pl, pm);
    attn_combine<<<NROWS * D / 512, 256>>>(po, pl, pm, a16);
    // out-proj + residual(x) -> xmid (fp32)  (128x64 tiles, 3 CTAs/SM)
    hmma_gemm<<<ggrid, 256, GSMEM_B>>>(a16, wt16 + 3*(size_t)D*D, bo, x, xmid, nullptr, 0);
    // LN2 -> fp16
    ln_f16<<<NROWS, 256>>>(xmid, ln2_w, ln2_b, xn16);
    // MLP up + ReLU -> fp16 hidden
    hmma_gemm<<<ggrid, 256, GSMEM_B>>>(xn16, wt16 + 4*(size_t)D*D, b1, nullptr,
                                       nullptr, h16, 1);
    // MLP down + residual(xmid) -> out (fp32)
    hmma_gemm<<<ggrid, 256, GSMEM_B>>>(h16, wt16 + 5*(size_t)D*D, b2, xmid,
                                       out, nullptr, 0);
}

// round 16
// speedup vs baseline: 1.0726x; 1.0726x over previous
#include <cuda_runtime.h>
#include <cuda_fp16.h>
#include <stdint.h>
#include <math.h>

#define D 768
#define BATCH 2
#define SEQ 2048
#define NROWS (BATCH*SEQ)   // 4096
#define NHEADS 12
#define HDIM 64
#define EPS 1e-5f

#define BK 64
#define KSTAGES (D/BK)      // 12

// softmax scale folded into Q and bias: logits computed in log2 domain
#define QSCALE 0.1803368801111204f   // 0.125 * log2(e)

// ---------------- scratch ----------------
__device__ float g_xmid[NROWS*D];
__device__ __half g_xn16[NROWS*D];
__device__ __half g_q16[NROWS*D], g_k16[NROWS*D], g_v16[NROWS*D];
__device__ __half g_a16[NROWS*D];
__device__ __half g_h16[NROWS*D];
__device__ __half g_wt16[6*D*D];
__device__ unsigned char g_mask8[(size_t)BATCH*SEQ*SEQ];

// ---------------- PTX helpers ----------------
__device__ __forceinline__ uint32_t smem_u32(const void* p) {
    uint32_t a;
    asm("{ .reg .u64 t; cvta.to.shared.u64 t, %1; cvt.u32.u64 %0, t; }" : "=r"(a) : "l"(p));
    return a;
}
__device__ __forceinline__ void cp_async16(uint32_t dst, const void* src) {
    asm volatile("cp.async.ca.shared.global [%0], [%1], 16;\n" :: "r"(dst), "l"(src));
}
__device__ __forceinline__ void cp_commit() { asm volatile("cp.async.commit_group;\n"); }
__device__ __forceinline__ void cp_wait0()  { asm volatile("cp.async.wait_group 0;\n" ::: "memory"); }
__device__ __forceinline__ void cp_wait1()  { asm volatile("cp.async.wait_group 1;\n" ::: "memory"); }

__device__ __forceinline__ void ldsm_x4(uint32_t addr, uint32_t* r) {
    asm volatile("ldmatrix.sync.aligned.m8n8.x4.shared.b16 {%0,%1,%2,%3}, [%4];"
                 : "=r"(r[0]), "=r"(r[1]), "=r"(r[2]), "=r"(r[3]) : "r"(addr));
}
__device__ __forceinline__ void ldsm_x4t(uint32_t addr, uint32_t* r) {
    asm volatile("ldmatrix.sync.aligned.m8n8.x4.trans.shared.b16 {%0,%1,%2,%3}, [%4];"
                 : "=r"(r[0]), "=r"(r[1]), "=r"(r[2]), "=r"(r[3]) : "r"(addr));
}
__device__ __forceinline__ void mma_f16(float* c, const uint32_t* a, uint32_t b0, uint32_t b1) {
    asm volatile("mma.sync.aligned.m16n8k16.row.col.f32.f16.f16.f32 "
                 "{%0,%1,%2,%3},{%4,%5,%6,%7},{%8,%9},{%0,%1,%2,%3};"
                 : "+f"(c[0]), "+f"(c[1]), "+f"(c[2]), "+f"(c[3])
                 : "r"(a[0]), "r"(a[1]), "r"(a[2]), "r"(a[3]), "r"(b0), "r"(b1));
}

__device__ __forceinline__ uint32_t pack_half2(float a, float b) {
    __half2 h = __floats2half2_rn(a, b);
    return *(uint32_t*)&h;
}

// ---------------- weight transpose -> fp16 (all 6 in one launch) ----------------
__global__ void transpose6(const float* __restrict__ w0, const float* __restrict__ w1,
                           const float* __restrict__ w2, const float* __restrict__ w3,
                           const float* __restrict__ w4, const float* __restrict__ w5,
                           __half* __restrict__ T16) {
    __shared__ float tile[32][33];
    int z = blockIdx.z;
    const float* W = (z == 0) ? w0 : (z == 1) ? w1 : (z == 2) ? w2
                   : (z == 3) ? w3 : (z == 4) ? w4 : w5;
    __half* t16 = T16 + (size_t)z * D * D;
    int bx = blockIdx.x * 32, by = blockIdx.y * 32;
    int tx = threadIdx.x, ty = threadIdx.y;
    #pragma unroll
    for (int i = 0; i < 4; i++)
        tile[ty + 8*i][tx] = W[(size_t)(by + ty + 8*i) * D + bx + tx];
    __syncthreads();
    #pragma unroll
    for (int i = 0; i < 4; i++) {
        float v = tile[tx][ty + 8*i];
        t16[(size_t)(bx + ty + 8*i) * D + by + tx] = __float2half(v);
    }
}

// ---------------- mask int32 -> int8 ----------------
__global__ void mask_pack(const int* __restrict__ m, unsigned char* __restrict__ m8, int n4) {
    int i = blockIdx.x * blockDim.x + threadIdx.x;
    if (i < n4) {
        int4 v = *(const int4*)(m + (size_t)i * 4);
        uchar4 o;
        o.x = (unsigned char)v.x; o.y = (unsigned char)v.y;
        o.z = (unsigned char)v.z; o.w = (unsigned char)v.w;
        *(uchar4*)(m8 + (size_t)i * 4) = o;
    }
}

// ---------------- LayerNorm -> fp16 ----------------
__global__ void ln_f16(const float* __restrict__ x, const float* __restrict__ w,
                       const float* __restrict__ b, __half* __restrict__ y16) {
    __shared__ float sh_s[8], sh_ss[8];
    __shared__ float mu_sh, rstd_sh;
    int row = blockIdx.x;
    const float* xr = x + (size_t)row * D;
    int t = threadIdx.x;
    float v0 = xr[t], v1 = xr[t + 256], v2 = xr[t + 512];
    float s  = v0 + v1 + v2;
    float ss = v0*v0 + v1*v1 + v2*v2;
    #pragma unroll
    for (int o = 16; o > 0; o >>= 1) {
        s  += __shfl_xor_sync(0xffffffffu, s,  o);
        ss += __shfl_xor_sync(0xffffffffu, ss, o);
    }
    int wid = t >> 5, lane = t & 31;
    if (lane == 0) { sh_s[wid] = s; sh_ss[wid] = ss; }
    __syncthreads();
    if (t == 0) {
        float S = 0.f, SS = 0.f;
        #pragma unroll
        for (int i = 0; i < 8; i++) { S += sh_s[i]; SS += sh_ss[i]; }
        float mu = S / (float)D;
        float var = SS / (float)D - mu * mu;
        mu_sh = mu; rstd_sh = rsqrtf(var + EPS);
    }
    __syncthreads();
    float mu = mu_sh, rs = rstd_sh;
    size_t base = (size_t)row * D;
    #pragma unroll
    for (int i = 0; i < 3; i++) {
        int c = t + 256 * i;
        float v = (i == 0) ? v0 : (i == 1) ? v1 : v2;
        float o = (v - mu) * rs * w[c] + b[c];
        y16[base + c] = __float2half(o);
    }
}

// =============== fp16 HMMA GEMM core A: CTA 128x128, BK=64 ======================
#define STG_A 32768            // A 16KB + B 16KB
#define GSMEM_A (2*STG_A)      // 64KB

__device__ __forceinline__ void gemm128(
    const __half* __restrict__ A16, const __half* __restrict__ W16,
    const float* __restrict__ bias, float* __restrict__ Cf,
    __half* __restrict__ C16, int brow, int bcol, uint32_t sb, float oscale)
{
    int t = threadIdx.x;
    int wid = t >> 5, lane = t & 31;
    int wm = wid & 1, wn = wid >> 1;

    float acc[4][4][4];
    #pragma unroll
    for (int i = 0; i < 4; i++)
        #pragma unroll
        for (int j = 0; j < 4; j++)
            #pragma unroll
            for (int c = 0; c < 4; c++) acc[i][j][c] = 0.f;

    auto load_stage = [&](int s) {
        uint32_t base = sb + (uint32_t)((s & 1) * STG_A);
        int k0 = s * BK;
        // A: 128 rows x 128B = 1024 chunks; B same. 4 A-chunks + 4 B-chunks per thread.
        #pragma unroll
        for (int i = 0; i < 4; i++) {
            int id = t + i * 256;
            int r = id >> 3, c = id & 7;
            uint32_t so = (uint32_t)(r * 128 + ((c ^ (r & 7)) * 16));
            cp_async16(base + so,         A16 + (size_t)(brow + r) * D + k0 + c * 8);
            cp_async16(base + 16384 + so, W16 + (size_t)(bcol + r) * D + k0 + c * 8);
        }
        cp_commit();
    };

    load_stage(0);

    for (int s = 0; s < KSTAGES; s++) {
        if (s < KSTAGES - 1) load_stage(s + 1);
        if (s < KSTAGES - 1) cp_wait1(); else cp_wait0();
        __syncthreads();

        uint32_t base = sb + (uint32_t)((s & 1) * STG_A);
        #pragma unroll
        for (int kstep = 0; kstep < 4; kstep++) {
            uint32_t af[4][4];
            #pragma unroll
            for (int mt = 0; mt < 4; mt++) {
                int row = wm * 64 + mt * 16 + (lane & 15);
                int ch = kstep * 2 + (lane >> 4);
                uint32_t so = (uint32_t)(row * 128 + ((ch ^ (row & 7)) * 16));
                ldsm_x4(base + so, af[mt]);
            }
            uint32_t bf[2][4];
            #pragma unroll
            for (int nt2 = 0; nt2 < 2; nt2++) {
                int row = wn * 32 + nt2 * 16 + (lane & 7) + ((lane & 16) ? 8 : 0);
                int ch = kstep * 2 + ((lane >> 3) & 1);
                uint32_t so = (uint32_t)(row * 128 + ((ch ^ (row & 7)) * 16));
                ldsm_x4(base + 16384 + so, bf[nt2]);
            }
            #pragma unroll
            for (int mt = 0; mt < 4; mt++)
                #pragma unroll
                for (int nt = 0; nt < 4; nt++)
                    mma_f16(acc[mt][nt], af[mt],
                            bf[nt >> 1][(nt & 1) * 2], bf[nt >> 1][(nt & 1) * 2 + 1]);
        }
        __syncthreads();
    }

    #pragma unroll
    for (int mt = 0; mt < 4; mt++) {
        #pragma unroll
        for (int nt = 0; nt < 4; nt++) {
            float* c = acc[mt][nt];
            int col = bcol + wn * 32 + nt * 8 + (lane & 3) * 2;
            #pragma unroll
            for (int half = 0; half < 2; half++) {
                int row = brow + wm * 64 + mt * 16 + (lane >> 2) + half * 8;
                float2 o;
                o.x = c[half * 2 + 0];
                o.y = c[half * 2 + 1];
                const float2 bb = *(const float2*)(bias + col);
                o.x = (o.x + bb.x) * oscale;
                o.y = (o.y + bb.y) * oscale;
                size_t gidx = (size_t)row * D + col;
                if (Cf)  *(float2*)(Cf + gidx) = o;
                if (C16) *(uint32_t*)(C16 + gidx) = pack_half2(o.x, o.y);
            }
        }
    }
}

// Merged QKV: grid (18, 32); sel = x/6, col tile = x%6. Q pre-scaled by QSCALE.
__global__ void __launch_bounds__(256, 2)
qkv_gemm(const __half* __restrict__ A16, const __half* __restrict__ Wt16,
         const float* __restrict__ bq, const float* __restrict__ bk, const float* __restrict__ bv,
         __half* __restrict__ q16, __half* __restrict__ k16, __half* __restrict__ v16)
{
    extern __shared__ char smem[];
    int sel = blockIdx.x / 6;
    int bcol = (blockIdx.x % 6) * 128;
    const __half* W = Wt16 + (size_t)sel * D * D;
    const float* bias = (sel == 0) ? bq : (sel == 1) ? bk : bv;
    __half* C16 = (sel == 0) ? q16 : (sel == 1) ? k16 : v16;
    float oscale = (sel == 0) ? QSCALE : 1.0f;
    gemm128(A16, W, bias, nullptr, C16, blockIdx.y * 128, bcol, smem_u32(smem), oscale);
}

// =============== fp16 HMMA GEMM core B: CTA 128x64, BK=64, 3 CTAs/SM ============
#define STG_B 24576            // A 16KB + B 8KB
#define GSMEM_B (2*STG_B)      // 48KB

__global__ void __launch_bounds__(256, 3)
hmma_gemm(const __half* __restrict__ A16, const __half* __restrict__ W16,
          const float* __restrict__ bias, const float* __restrict__ res,
          float* __restrict__ Cf, __half* __restrict__ C16, int relu)
{
    extern __shared__ char smem[];
    uint32_t sb = smem_u32(smem);
    int t = threadIdx.x;
    int wid = t >> 5, lane = t & 31;
    int wm = wid & 3, wn = wid >> 2;
    int brow = blockIdx.y * 128, bcol = blockIdx.x * 64;

    float acc[2][4][4];
    #pragma unroll
    for (int i = 0; i < 2; i++)
        #pragma unroll
        for (int j = 0; j < 4; j++)
            #pragma unroll
            for (int c = 0; c < 4; c++) acc[i][j][c] = 0.f;

    auto load_stage = [&](int s) {
        uint32_t base = sb + (uint32_t)((s & 1) * STG_B);
        int k0 = s * BK;
        // A: 128 rows x 128B = 1024 chunks -> 4/thread
        #pragma unroll
        for (int i = 0; i < 4; i++) {
            int id = t + i * 256;
            int r = id >> 3, c = id & 7;
            uint32_t so = (uint32_t)(r * 128 + ((c ^ (r & 7)) * 16));
            cp_async16(base + so, A16 + (size_t)(brow + r) * D + k0 + c * 8);
        }
        // B: 64 rows x 128B = 512 chunks -> 2/thread
        #pragma unroll
        for (int i = 0; i < 2; i++) {
            int id = t + i * 256;
            int r = id >> 3, c = id & 7;
            uint32_t so = (uint32_t)(r * 128 + ((c ^ (r & 7)) * 16));
            cp_async16(base + 16384 + so, W16 + (size_t)(bcol + r) * D + k0 + c * 8);
        }
        cp_commit();
    };

    load_stage(0);

    for (int s = 0; s < KSTAGES; s++) {
        if (s < KSTAGES - 1) load_stage(s + 1);
        if (s < KSTAGES - 1) cp_wait1(); else cp_wait0();
        __syncthreads();

        uint32_t base = sb + (uint32_t)((s & 1) * STG_B);
        #pragma unroll
        for (int kstep = 0; kstep < 4; kstep++) {
            uint32_t af[2][4];
            #pragma unroll
            for (int mt = 0; mt < 2; mt++) {
                int row = wm * 32 + mt * 16 + (lane & 15);
                int ch = kstep * 2 + (lane >> 4);
                uint32_t so = (uint32_t)(row * 128 + ((ch ^ (row & 7)) * 16));
                ldsm_x4(base + so, af[mt]);
            }
            uint32_t bf[2][4];
            #pragma unroll
            for (int nt2 = 0; nt2 < 2; nt2++) {
                int row = wn * 32 + nt2 * 16 + (lane & 7) + ((lane & 16) ? 8 : 0);
                int ch = kstep * 2 + ((lane >> 3) & 1);
                uint32_t so = (uint32_t)(row * 128 + ((ch ^ (row & 7)) * 16));
                ldsm_x4(base + 16384 + so, bf[nt2]);
            }
            #pragma unroll
            for (int mt = 0; mt < 2; mt++)
                #pragma unroll
                for (int nt = 0; nt < 4; nt++)
                    mma_f16(acc[mt][nt], af[mt],
                            bf[nt >> 1][(nt & 1) * 2], bf[nt >> 1][(nt & 1) * 2 + 1]);
        }
        __syncthreads();
    }

    #pragma unroll
    for (int mt = 0; mt < 2; mt++) {
        #pragma unroll
        for (int nt = 0; nt < 4; nt++) {
            float* c = acc[mt][nt];
            int col = bcol + wn * 32 + nt * 8 + (lane & 3) * 2;
            #pragma unroll
            for (int half = 0; half < 2; half++) {
                int row = brow + wm * 32 + mt * 16 + (lane >> 2) + half * 8;
                float2 o;
                o.x = c[half * 2 + 0];
                o.y = c[half * 2 + 1];
                const float2 bb = *(const float2*)(bias + col);
                o.x += bb.x; o.y += bb.y;
                size_t gidx = (size_t)row * D + col;
                if (res) {
                    float2 rv = *(const float2*)(res + gidx);
                    o.x += rv.x; o.y += rv.y;
                }
                if (relu) { o.x = fmaxf(o.x, 0.f); o.y = fmaxf(o.y, 0.f); }
                if (Cf)  *(float2*)(Cf + gidx) = o;
                if (C16) *(uint32_t*)(C16 + gidx) = pack_half2(o.x, o.y);
            }
        }
    }
}

// ---------------- fp16 tensor-core flash attention (log2-domain softmax) ---------
#define AOFF_Q    0
#define AOFF_KV   16384              // + buf*16384 : K(8K) V(8K)
#define AOFF_BIAS 49152              // 128 rows x 272B
#define AOFF_MASK 83968              // 128 rows x 80B
#define ASMEM     94208

__global__ void __launch_bounds__(256, 2)
attn_mma(const __half* __restrict__ q16, const __half* __restrict__ k16,
         const __half* __restrict__ v16,
         const float* __restrict__ bias, const unsigned char* __restrict__ mask8,
         __half* __restrict__ out16)
{
    extern __shared__ char smem[];
    uint32_t sb = smem_u32(smem);
    int t = threadIdx.x;
    int w = t >> 5, lane = t & 31;

    int qt = blockIdx.x;
    int hb = blockIdx.y;
    int hd = hb >> 1;
    int b  = hb & 1;

    size_t qrow0 = (size_t)b * SEQ + qt * 128;
    const __half* qg = q16 + qrow0 * D + hd * HDIM;
    const __half* kg = k16 + (size_t)b * SEQ * D + hd * HDIM;
    const __half* vg = v16 + (size_t)b * SEQ * D + hd * HDIM;
    const float* biasbase = bias + ((size_t)(hd * BATCH + b) * SEQ + qt * 128) * SEQ;
    const unsigned char* maskbase = mask8 + ((size_t)b * SEQ + qt * 128) * SEQ;

    #pragma unroll
    for (int i = 0; i < 4; i++) {
        int id = t + i * 256;
        int row = id >> 3, c = id & 7;
        uint32_t so = (uint32_t)(row * 128 + ((c ^ (row & 7)) * 16));
        cp_async16(sb + AOFF_Q + so, qg + (size_t)row * D + c * 8);
    }
    cp_commit();

    auto load_kv = [&](int kt) {
        uint32_t base = sb + AOFF_KV + (uint32_t)((kt & 1) * 16384);
        #pragma unroll
        for (int i = 0; i < 2; i++) {
            int id = t + i * 256;
            int row = id >> 3, c = id & 7;
            uint32_t so = (uint32_t)(row * 128 + ((c ^ (row & 7)) * 16));
            size_t g = (size_t)(kt * 64 + row) * D + c * 8;
            cp_async16(base + so,        kg + g);
            cp_async16(base + 8192 + so, vg + g);
        }
        cp_commit();
    };

    auto load_bm = [&](int kt) {
        #pragma unroll
        for (int i = 0; i < 8; i++) {
            int id = t + i * 256;
            int row = id >> 4, c = id & 15;
            cp_async16(sb + AOFF_BIAS + (uint32_t)(row * 272 + c * 16),
                       biasbase + (size_t)row * SEQ + kt * 64 + c * 4);
        }
        #pragma unroll
        for (int i = 0; i < 2; i++) {
            int id = t + i * 256;
            int row = id >> 2, c = id & 3;
            cp_async16(sb + AOFF_MASK + (uint32_t)(row * 80 + c * 16),
                       maskbase + (size_t)row * SEQ + kt * 64 + c * 16);
        }
        cp_commit();
    };

    load_kv(0);
    load_bm(0);
    load_kv(1);

    float accO[8][4];
    #pragma unroll
    for (int j = 0; j < 8; j++)
        #pragma unroll
        for (int c = 0; c < 4; c++) accO[j][c] = 0.f;
    float m[2] = {-1e30f, -1e30f}, lsum[2] = {0.f, 0.f};

    const int NKT = SEQ / 64;
    for (int kt = 0; kt < NKT; kt++) {
        if (kt < NKT - 1) cp_wait1(); else cp_wait0();
        __syncthreads();

        uint32_t base = sb + AOFF_KV + (uint32_t)((kt & 1) * 16384);

        // ---- S = Q @ K^T  (Q pre-scaled; S in log2 domain) ----
        float s[8][4];
        #pragma unroll
        for (int j = 0; j < 8; j++)
            #pragma unroll
            for (int c = 0; c < 4; c++) s[j][c] = 0.f;

        #pragma unroll
        for (int kk = 0; kk < 4; kk++) {
            uint32_t qa[4];
            {
                int row = w * 16 + (lane & 15);
                int ch = kk * 2 + (lane >> 4);
                uint32_t so = (uint32_t)(row * 128 + ((ch ^ (row & 7)) * 16));
                ldsm_x4(sb + AOFF_Q + so, qa);
            }
            uint32_t kb[4][4];
            #pragma unroll
            for (int np = 0; np < 4; np++) {
                int row = np * 16 + (lane & 7) + ((lane & 16) ? 8 : 0);
                int ch = kk * 2 + ((lane >> 3) & 1);
                uint32_t so = (uint32_t)(row * 128 + ((ch ^ (row & 7)) * 16));
                ldsm_x4(base + so, kb[np]);
            }
            #pragma unroll
            for (int j = 0; j < 8; j++)
                mma_f16(s[j], qa, kb[j >> 1][(j & 1) * 2], kb[j >> 1][(j & 1) * 2 + 1]);
        }

        // ---- softmax in log2 domain ----
        #pragma unroll
        for (int hh = 0; hh < 2; hh++) {
            int row = w * 16 + (lane >> 2) + hh * 8;
            const float* bsm = (const float*)(smem + AOFF_BIAS + (size_t)row * 272)
                               + (lane & 3) * 2;
            const unsigned char* msm = (const unsigned char*)(smem + AOFF_MASK
                               + (size_t)row * 80) + (lane & 3) * 2;
            float mx = -1e30f;
            #pragma unroll
            for (int j = 0; j < 8; j++) {
                float2 bb = *(const float2*)(bsm + j * 8);
                uchar2 mm = *(const uchar2*)(msm + j * 8);
                float v0 = mm.x ? fmaf(bb.x, QSCALE, s[j][hh*2+0]) : -1e30f;
                float v1 = mm.y ? fmaf(bb.y, QSCALE, s[j][hh*2+1]) : -1e30f;
                s[j][hh*2+0] = v0; s[j][hh*2+1] = v1;
                mx = fmaxf(mx, fmaxf(v0, v1));
            }
            mx = fmaxf(mx, __shfl_xor_sync(0xffffffffu, mx, 1));
            mx = fmaxf(mx, __shfl_xor_sync(0xffffffffu, mx, 2));
            float mn = fmaxf(m[hh], mx);
            float alpha = exp2f(m[hh] - mn);
            m[hh] = mn;
            float rs = 0.f;
            #pragma unroll
            for (int j = 0; j < 8; j++) {
                float e0 = exp2f(s[j][hh*2+0] - mn);
                float e1 = exp2f(s[j][hh*2+1] - mn);
                s[j][hh*2+0] = e0; s[j][hh*2+1] = e1;
                rs += e0 + e1;
            }
            rs += __shfl_xor_sync(0xffffffffu, rs, 1);
            rs += __shfl_xor_sync(0xffffffffu, rs, 2);
            lsum[hh] = lsum[hh] * alpha + rs;
            #pragma unroll
            for (int j = 0; j < 8; j++) {
                accO[j][hh*2+0] *= alpha;
                accO[j][hh*2+1] *= alpha;
            }
        }

        // ---- O += P @ V ----
        #pragma unroll
        for (int kk = 0; kk < 4; kk++) {
            int j0 = kk * 2, j1 = kk * 2 + 1;
            uint32_t pa[4];
            pa[0] = pack_half2(s[j0][0], s[j0][1]);
            pa[1] = pack_half2(s[j0][2], s[j0][3]);
            pa[2] = pack_half2(s[j1][0], s[j1][1]);
            pa[3] = pack_half2(s[j1][2], s[j1][3]);
            uint32_t vb[4][4];
            #pragma unroll
            for (int np = 0; np < 4; np++) {
                int i = lane >> 3, jj = lane & 7;
                int tok = kk * 16 + (i & 1) * 8 + jj;
                int ch = np * 2 + (i >> 1);
                uint32_t so = (uint32_t)(tok * 128 + ((ch ^ (tok & 7)) * 16));
                ldsm_x4t(base + 8192 + so, vb[np]);
            }
            #pragma unroll
            for (int j = 0; j < 8; j++)
                mma_f16(accO[j], pa, vb[j >> 1][(j & 1) * 2], vb[j >> 1][(j & 1) * 2 + 1]);
        }
        __syncthreads();

        if (kt + 1 < NKT) load_bm(kt + 1);
        if (kt + 2 < NKT) load_kv(kt + 2);
    }

    // ---- epilogue: normalize + fp16 write ----
    #pragma unroll
    for (int hh = 0; hh < 2; hh++) {
        float inv = 1.0f / lsum[hh];
        size_t row = qrow0 + w * 16 + (lane >> 2) + hh * 8;
        #pragma unroll
        for (int j = 0; j < 8; j++) {
            int col = hd * HDIM + j * 8 + (lane & 3) * 2;
            *(uint32_t*)(out16 + row * D + col) =
                pack_half2(accO[j][hh*2+0] * inv, accO[j][hh*2+1] * inv);
        }
    }
}

// ---------------- host launcher --------------------------------------------------
extern "C" void kernel_launch(void* const* d_in, const int* in_sizes, int n_in,
                              void* d_out, int out_size) {
    const float* x     = (const float*)d_in[0];
    const float* bias  = (const float*)d_in[1];
    const int*   mask  = (const int*)d_in[2];
    const float* ln1_w = (const float*)d_in[3];
    const float* ln1_b = (const float*)d_in[4];
    const float* wq    = (const float*)d_in[5];
    const float* bq    = (const float*)d_in[6];
    const float* wk    = (const float*)d_in[7];
    const float* bk    = (const float*)d_in[8];
    const float* wv    = (const float*)d_in[9];
    const float* bv    = (const float*)d_in[10];
    const float* wo    = (const float*)d_in[11];
    const float* bo    = (const float*)d_in[12];
    const float* ln2_w = (const float*)d_in[13];
    const float* ln2_b = (const float*)d_in[14];
    const float* w1    = (const float*)d_in[15];
    const float* b1    = (const float*)d_in[16];
    const float* w2    = (const float*)d_in[17];
    const float* b2    = (const float*)d_in[18];
    float* out = (float*)d_out;

    float *xmid;
    __half *xn16, *q16, *k16, *v16, *a16, *h16, *wt16;
    unsigned char* mask8;
    cudaGetSymbolAddress((void**)&xmid, g_xmid);
    cudaGetSymbolAddress((void**)&xn16, g_xn16);
    cudaGetSymbolAddress((void**)&q16,  g_q16);
    cudaGetSymbolAddress((void**)&k16,  g_k16);
    cudaGetSymbolAddress((void**)&v16,  g_v16);
    cudaGetSymbolAddress((void**)&a16,  g_a16);
    cudaGetSymbolAddress((void**)&h16,  g_h16);
    cudaGetSymbolAddress((void**)&wt16, g_wt16);
    cudaGetSymbolAddress((void**)&mask8, g_mask8);

    cudaFuncSetAttribute(hmma_gemm, cudaFuncAttributeMaxDynamicSharedMemorySize, GSMEM_B);
    cudaFuncSetAttribute(qkv_gemm,  cudaFuncAttributeMaxDynamicSharedMemorySize, GSMEM_A);
    cudaFuncSetAttribute(attn_mma,  cudaFuncAttributeMaxDynamicSharedMemorySize, ASMEM);

    dim3 tgrid(24, 24, 6), tblk(32, 8);
    transpose6<<<tgrid, tblk>>>(wq, wk, wv, wo, w1, w2, wt16);
    mask_pack<<<(BATCH*SEQ*SEQ/4 + 255)/256, 256>>>(mask, mask8, BATCH*SEQ*SEQ/4);

    dim3 ggrid(D / 64, NROWS / 128);     // (12, 32) = 384
    dim3 qgrid(18, NROWS / 128);         // (18, 32) = 576

    // LN1 -> fp16
    ln_f16<<<NROWS, 256>>>(x, ln1_w, ln1_b, xn16);
    // merged QKV projections (128x128 tiles, BK=64; Q pre-scaled)
    qkv_gemm<<<qgrid, 256, GSMEM_A>>>(xn16, wt16, bq, bk, bv, q16, k16, v16);
    // attention
    dim3 attn_grid(SEQ / 128, NHEADS * BATCH);  // (16, 24)
    attn_mma<<<attn_grid, 256, ASMEM>>>(q16, k16, v16, bias, mask8, a16);
    // out-proj + residual(x) -> xmid (fp32)  (128x64, BK=64, 3 CTAs/SM)
    hmma_gemm<<<ggrid, 256, GSMEM_B>>>(a16, wt16 + 3*(size_t)D*D, bo, x, xmid, nullptr, 0);
    // LN2 -> fp16
    ln_f16<<<NROWS, 256>>>(xmid, ln2_w, ln2_b, xn16);
    // MLP up + ReLU -> fp16 hidden
    hmma_gemm<<<ggrid, 256, GSMEM_B>>>(xn16, wt16 + 4*(size_t)D*D, b1, nullptr,
                                       nullptr, h16, 1);
    // MLP down + residual(xmid) -> out (fp32)
    hmma_gemm<<<ggrid, 256, GSMEM_B>>>(h16, wt16 + 5*(size_t)D*D, b2, xmid,
                                       out, nullptr, 0);
}

// round 17
// speedup vs baseline: 1.1075x; 1.0325x over previous
#include <cuda_runtime.h>
#include <cuda_fp16.h>
#include <stdint.h>
#include <math.h>

#define D 768
#define BATCH 2
#define SEQ 2048
#define NROWS (BATCH*SEQ)   // 4096
#define NHEADS 12
#define HDIM 64
#define EPS 1e-5f

#define BK 64
#define KSTAGES (D/BK)      // 12

// softmax scale folded into Q and bias: logits computed in log2 domain
#define QSCALE 0.1803368801111204f   // 0.125 * log2(e)

// ---------------- scratch ----------------
__device__ float g_xmid[NROWS*D];
__device__ __half g_xn16[NROWS*D];
__device__ __half g_q16[NROWS*D], g_k16[NROWS*D], g_v16[NROWS*D];
__device__ __half g_a16[NROWS*D];
__device__ __half g_h16[NROWS*D];
__device__ __half g_wt16[6*D*D];
__device__ unsigned char g_mask8[(size_t)BATCH*SEQ*SEQ];

// ---------------- PTX helpers ----------------
__device__ __forceinline__ uint32_t smem_u32(const void* p) {
    uint32_t a;
    asm("{ .reg .u64 t; cvta.to.shared.u64 t, %1; cvt.u32.u64 %0, t; }" : "=r"(a) : "l"(p));
    return a;
}
__device__ __forceinline__ void cp_async16(uint32_t dst, const void* src) {
    asm volatile("cp.async.ca.shared.global [%0], [%1], 16;\n" :: "r"(dst), "l"(src));
}
__device__ __forceinline__ void cp_commit() { asm volatile("cp.async.commit_group;\n"); }
__device__ __forceinline__ void cp_wait0()  { asm volatile("cp.async.wait_group 0;\n" ::: "memory"); }
__device__ __forceinline__ void cp_wait1()  { asm volatile("cp.async.wait_group 1;\n" ::: "memory"); }

__device__ __forceinline__ void ldsm_x4(uint32_t addr, uint32_t* r) {
    asm volatile("ldmatrix.sync.aligned.m8n8.x4.shared.b16 {%0,%1,%2,%3}, [%4];"
                 : "=r"(r[0]), "=r"(r[1]), "=r"(r[2]), "=r"(r[3]) : "r"(addr));
}
__device__ __forceinline__ void ldsm_x4t(uint32_t addr, uint32_t* r) {
    asm volatile("ldmatrix.sync.aligned.m8n8.x4.trans.shared.b16 {%0,%1,%2,%3}, [%4];"
                 : "=r"(r[0]), "=r"(r[1]), "=r"(r[2]), "=r"(r[3]) : "r"(addr));
}
__device__ __forceinline__ void mma_f16(float* c, const uint32_t* a, uint32_t b0, uint32_t b1) {
    asm volatile("mma.sync.aligned.m16n8k16.row.col.f32.f16.f16.f32 "
                 "{%0,%1,%2,%3},{%4,%5,%6,%7},{%8,%9},{%0,%1,%2,%3};"
                 : "+f"(c[0]), "+f"(c[1]), "+f"(c[2]), "+f"(c[3])
                 : "r"(a[0]), "r"(a[1]), "r"(a[2]), "r"(a[3]), "r"(b0), "r"(b1));
}

__device__ __forceinline__ uint32_t pack_half2(float a, float b) {
    __half2 h = __floats2half2_rn(a, b);
    return *(uint32_t*)&h;
}

// ---------------- weight transpose -> fp16 (all 6 in one launch) ----------------
__global__ void transpose6(const float* __restrict__ w0, const float* __restrict__ w1,
                           const float* __restrict__ w2, const float* __restrict__ w3,
                           const float* __restrict__ w4, const float* __restrict__ w5,
                           __half* __restrict__ T16) {
    __shared__ float tile[32][33];
    int z = blockIdx.z;
    const float* W = (z == 0) ? w0 : (z == 1) ? w1 : (z == 2) ? w2
                   : (z == 3) ? w3 : (z == 4) ? w4 : w5;
    __half* t16 = T16 + (size_t)z * D * D;
    int bx = blockIdx.x * 32, by = blockIdx.y * 32;
    int tx = threadIdx.x, ty = threadIdx.y;
    #pragma unroll
    for (int i = 0; i < 4; i++)
        tile[ty + 8*i][tx] = W[(size_t)(by + ty + 8*i) * D + bx + tx];
    __syncthreads();
    #pragma unroll
    for (int i = 0; i < 4; i++) {
        float v = tile[tx][ty + 8*i];
        t16[(size_t)(bx + ty + 8*i) * D + by + tx] = __float2half(v);
    }
}

// ---------------- mask int32 -> int8 ----------------
__global__ void mask_pack(const int* __restrict__ m, unsigned char* __restrict__ m8, int n4) {
    int i = blockIdx.x * blockDim.x + threadIdx.x;
    if (i < n4) {
        int4 v = *(const int4*)(m + (size_t)i * 4);
        uchar4 o;
        o.x = (unsigned char)v.x; o.y = (unsigned char)v.y;
        o.z = (unsigned char)v.z; o.w = (unsigned char)v.w;
        *(uchar4*)(m8 + (size_t)i * 4) = o;
    }
}

// ---------------- LayerNorm -> fp16 ----------------
__global__ void ln_f16(const float* __restrict__ x, const float* __restrict__ w,
                       const float* __restrict__ b, __half* __restrict__ y16) {
    __shared__ float sh_s[8], sh_ss[8];
    __shared__ float mu_sh, rstd_sh;
    int row = blockIdx.x;
    const float* xr = x + (size_t)row * D;
    int t = threadIdx.x;
    float v0 = xr[t], v1 = xr[t + 256], v2 = xr[t + 512];
    float s  = v0 + v1 + v2;
    float ss = v0*v0 + v1*v1 + v2*v2;
    #pragma unroll
    for (int o = 16; o > 0; o >>= 1) {
        s  += __shfl_xor_sync(0xffffffffu, s,  o);
        ss += __shfl_xor_sync(0xffffffffu, ss, o);
    }
    int wid = t >> 5, lane = t & 31;
    if (lane == 0) { sh_s[wid] = s; sh_ss[wid] = ss; }
    __syncthreads();
    if (t == 0) {
        float S = 0.f, SS = 0.f;
        #pragma unroll
        for (int i = 0; i < 8; i++) { S += sh_s[i]; SS += sh_ss[i]; }
        float mu = S / (float)D;
        float var = SS / (float)D - mu * mu;
        mu_sh = mu; rstd_sh = rsqrtf(var + EPS);
    }
    __syncthreads();
    float mu = mu_sh, rs = rstd_sh;
    size_t base = (size_t)row * D;
    #pragma unroll
    for (int i = 0; i < 3; i++) {
        int c = t + 256 * i;
        float v = (i == 0) ? v0 : (i == 1) ? v1 : v2;
        float o = (v - mu) * rs * w[c] + b[c];
        y16[base + c] = __float2half(o);
    }
}

// =============== fp16 HMMA GEMM core A: CTA 128x128, BK=64 ======================
#define STG_A 32768            // A 16KB + B 16KB
#define GSMEM_A (2*STG_A)      // 64KB

__device__ __forceinline__ void gemm128(
    const __half* __restrict__ A16, const __half* __restrict__ W16,
    const float* __restrict__ bias, float* __restrict__ Cf,
    __half* __restrict__ C16, int brow, int bcol, uint32_t sb, float oscale)
{
    int t = threadIdx.x;
    int wid = t >> 5, lane = t & 31;
    int wm = wid & 1, wn = wid >> 1;

    float acc[4][4][4];
    #pragma unroll
    for (int i = 0; i < 4; i++)
        #pragma unroll
        for (int j = 0; j < 4; j++)
            #pragma unroll
            for (int c = 0; c < 4; c++) acc[i][j][c] = 0.f;

    auto load_stage = [&](int s) {
        uint32_t base = sb + (uint32_t)((s & 1) * STG_A);
        int k0 = s * BK;
        #pragma unroll
        for (int i = 0; i < 4; i++) {
            int id = t + i * 256;
            int r = id >> 3, c = id & 7;
            uint32_t so = (uint32_t)(r * 128 + ((c ^ (r & 7)) * 16));
            cp_async16(base + so,         A16 + (size_t)(brow + r) * D + k0 + c * 8);
            cp_async16(base + 16384 + so, W16 + (size_t)(bcol + r) * D + k0 + c * 8);
        }
        cp_commit();
    };

    load_stage(0);

    for (int s = 0; s < KSTAGES; s++) {
        if (s < KSTAGES - 1) load_stage(s + 1);
        if (s < KSTAGES - 1) cp_wait1(); else cp_wait0();
        __syncthreads();

        uint32_t base = sb + (uint32_t)((s & 1) * STG_A);
        #pragma unroll
        for (int kstep = 0; kstep < 4; kstep++) {
            uint32_t af[4][4];
            #pragma unroll
            for (int mt = 0; mt < 4; mt++) {
                int row = wm * 64 + mt * 16 + (lane & 15);
                int ch = kstep * 2 + (lane >> 4);
                uint32_t so = (uint32_t)(row * 128 + ((ch ^ (row & 7)) * 16));
                ldsm_x4(base + so, af[mt]);
            }
            uint32_t bf[2][4];
            #pragma unroll
            for (int nt2 = 0; nt2 < 2; nt2++) {
                int row = wn * 32 + nt2 * 16 + (lane & 7) + ((lane & 16) ? 8 : 0);
                int ch = kstep * 2 + ((lane >> 3) & 1);
                uint32_t so = (uint32_t)(row * 128 + ((ch ^ (row & 7)) * 16));
                ldsm_x4(base + 16384 + so, bf[nt2]);
            }
            #pragma unroll
            for (int mt = 0; mt < 4; mt++)
                #pragma unroll
                for (int nt = 0; nt < 4; nt++)
                    mma_f16(acc[mt][nt], af[mt],
                            bf[nt >> 1][(nt & 1) * 2], bf[nt >> 1][(nt & 1) * 2 + 1]);
        }
        __syncthreads();
    }

    #pragma unroll
    for (int mt = 0; mt < 4; mt++) {
        #pragma unroll
        for (int nt = 0; nt < 4; nt++) {
            float* c = acc[mt][nt];
            int col = bcol + wn * 32 + nt * 8 + (lane & 3) * 2;
            #pragma unroll
            for (int half = 0; half < 2; half++) {
                int row = brow + wm * 64 + mt * 16 + (lane >> 2) + half * 8;
                float2 o;
                o.x = c[half * 2 + 0];
                o.y = c[half * 2 + 1];
                const float2 bb = *(const float2*)(bias + col);
                o.x = (o.x + bb.x) * oscale;
                o.y = (o.y + bb.y) * oscale;
                size_t gidx = (size_t)row * D + col;
                if (Cf)  *(float2*)(Cf + gidx) = o;
                if (C16) *(uint32_t*)(C16 + gidx) = pack_half2(o.x, o.y);
            }
        }
    }
}

// Merged QKV: grid (18, 32); sel = x/6, col tile = x%6. Q pre-scaled by QSCALE.
__global__ void __launch_bounds__(256, 2)
qkv_gemm(const __half* __restrict__ A16, const __half* __restrict__ Wt16,
         const float* __restrict__ bq, const float* __restrict__ bk, const float* __restrict__ bv,
         __half* __restrict__ q16, __half* __restrict__ k16, __half* __restrict__ v16)
{
    extern __shared__ char smem[];
    int sel = blockIdx.x / 6;
    int bcol = (blockIdx.x % 6) * 128;
    const __half* W = Wt16 + (size_t)sel * D * D;
    const float* bias = (sel == 0) ? bq : (sel == 1) ? bk : bv;
    __half* C16 = (sel == 0) ? q16 : (sel == 1) ? k16 : v16;
    float oscale = (sel == 0) ? QSCALE : 1.0f;
    gemm128(A16, W, bias, nullptr, C16, blockIdx.y * 128, bcol, smem_u32(smem), oscale);
}

// =============== fp16 HMMA GEMM core B: CTA 128x64, BK=64, 3 CTAs/SM ============
#define STG_B 24576            // A 16KB + B 8KB
#define GSMEM_B (2*STG_B)      // 48KB

__global__ void __launch_bounds__(256, 3)
hmma_gemm(const __half* __restrict__ A16, const __half* __restrict__ W16,
          const float* __restrict__ bias, const float* __restrict__ res,
          float* __restrict__ Cf, __half* __restrict__ C16, int relu)
{
    extern __shared__ char smem[];
    uint32_t sb = smem_u32(smem);
    int t = threadIdx.x;
    int wid = t >> 5, lane = t & 31;
    int wm = wid & 3, wn = wid >> 2;
    int brow = blockIdx.y * 128, bcol = blockIdx.x * 64;

    float acc[2][4][4];
    #pragma unroll
    for (int i = 0; i < 2; i++)
        #pragma unroll
        for (int j = 0; j < 4; j++)
            #pragma unroll
            for (int c = 0; c < 4; c++) acc[i][j][c] = 0.f;

    auto load_stage = [&](int s) {
        uint32_t base = sb + (uint32_t)((s & 1) * STG_B);
        int k0 = s * BK;
        #pragma unroll
        for (int i = 0; i < 4; i++) {
            int id = t + i * 256;
            int r = id >> 3, c = id & 7;
            uint32_t so = (uint32_t)(r * 128 + ((c ^ (r & 7)) * 16));
            cp_async16(base + so, A16 + (size_t)(brow + r) * D + k0 + c * 8);
        }
        #pragma unroll
        for (int i = 0; i < 2; i++) {
            int id = t + i * 256;
            int r = id >> 3, c = id & 7;
            uint32_t so = (uint32_t)(r * 128 + ((c ^ (r & 7)) * 16));
            cp_async16(base + 16384 + so, W16 + (size_t)(bcol + r) * D + k0 + c * 8);
        }
        cp_commit();
    };

    load_stage(0);

    for (int s = 0; s < KSTAGES; s++) {
        if (s < KSTAGES - 1) load_stage(s + 1);
        if (s < KSTAGES - 1) cp_wait1(); else cp_wait0();
        __syncthreads();

        uint32_t base = sb + (uint32_t)((s & 1) * STG_B);
        #pragma unroll
        for (int kstep = 0; kstep < 4; kstep++) {
            uint32_t af[2][4];
            #pragma unroll
            for (int mt = 0; mt < 2; mt++) {
                int row = wm * 32 + mt * 16 + (lane & 15);
                int ch = kstep * 2 + (lane >> 4);
                uint32_t so = (uint32_t)(row * 128 + ((ch ^ (row & 7)) * 16));
                ldsm_x4(base + so, af[mt]);
            }
            uint32_t bf[2][4];
            #pragma unroll
            for (int nt2 = 0; nt2 < 2; nt2++) {
                int row = wn * 32 + nt2 * 16 + (lane & 7) + ((lane & 16) ? 8 : 0);
                int ch = kstep * 2 + ((lane >> 3) & 1);
                uint32_t so = (uint32_t)(row * 128 + ((ch ^ (row & 7)) * 16));
                ldsm_x4(base + 16384 + so, bf[nt2]);
            }
            #pragma unroll
            for (int mt = 0; mt < 2; mt++)
                #pragma unroll
                for (int nt = 0; nt < 4; nt++)
                    mma_f16(acc[mt][nt], af[mt],
                            bf[nt >> 1][(nt & 1) * 2], bf[nt >> 1][(nt & 1) * 2 + 1]);
        }
        __syncthreads();
    }

    #pragma unroll
    for (int mt = 0; mt < 2; mt++) {
        #pragma unroll
        for (int nt = 0; nt < 4; nt++) {
            float* c = acc[mt][nt];
            int col = bcol + wn * 32 + nt * 8 + (lane & 3) * 2;
            #pragma unroll
            for (int half = 0; half < 2; half++) {
                int row = brow + wm * 32 + mt * 16 + (lane >> 2) + half * 8;
                float2 o;
                o.x = c[half * 2 + 0];
                o.y = c[half * 2 + 1];
                const float2 bb = *(const float2*)(bias + col);
                o.x += bb.x; o.y += bb.y;
                size_t gidx = (size_t)row * D + col;
                if (res) {
                    float2 rv = *(const float2*)(res + gidx);
                    o.x += rv.x; o.y += rv.y;
                }
                if (relu) { o.x = fmaxf(o.x, 0.f); o.y = fmaxf(o.y, 0.f); }
                if (Cf)  *(float2*)(Cf + gidx) = o;
                if (C16) *(uint32_t*)(C16 + gidx) = pack_half2(o.x, o.y);
            }
        }
    }
}

// ---------------- fp16 flash attention: 64q x 64k, 4 warps, 3 CTAs/SM -----------
#define AOFF_Q    0                 // 64 x 128B = 8KB
#define AOFF_KV   8192              // + buf*16384 : K(8K) V(8K), 2 bufs = 32KB
#define AOFF_BIAS 40960             // 64 rows x 272B = 17408
#define AOFF_MASK 58368             // 64 rows x 80B = 5120
#define ASMEM     63488

__global__ void __launch_bounds__(128, 3)
attn_mma(const __half* __restrict__ q16, const __half* __restrict__ k16,
         const __half* __restrict__ v16,
         const float* __restrict__ bias, const unsigned char* __restrict__ mask8,
         __half* __restrict__ out16)
{
    extern __shared__ char smem[];
    uint32_t sb = smem_u32(smem);
    int t = threadIdx.x;
    int w = t >> 5, lane = t & 31;

    int qt = blockIdx.x;          // 0..31 (64-row q tiles)
    int hb = blockIdx.y;
    int hd = hb >> 1;
    int b  = hb & 1;

    size_t qrow0 = (size_t)b * SEQ + qt * 64;
    const __half* qg = q16 + qrow0 * D + hd * HDIM;
    const __half* kg = k16 + (size_t)b * SEQ * D + hd * HDIM;
    const __half* vg = v16 + (size_t)b * SEQ * D + hd * HDIM;
    const float* biasbase = bias + ((size_t)(hd * BATCH + b) * SEQ + qt * 64) * SEQ;
    const unsigned char* maskbase = mask8 + ((size_t)b * SEQ + qt * 64) * SEQ;

    // Q tile: 64 rows x 8 chunks = 512, 4 per thread
    #pragma unroll
    for (int i = 0; i < 4; i++) {
        int id = t + i * 128;
        int row = id >> 3, c = id & 7;
        uint32_t so = (uint32_t)(row * 128 + ((c ^ (row & 7)) * 16));
        cp_async16(sb + AOFF_Q + so, qg + (size_t)row * D + c * 8);
    }
    cp_commit();

    auto load_kv = [&](int kt) {
        uint32_t base = sb + AOFF_KV + (uint32_t)((kt & 1) * 16384);
        #pragma unroll
        for (int i = 0; i < 4; i++) {
            int id = t + i * 128;
            int row = id >> 3, c = id & 7;
            uint32_t so = (uint32_t)(row * 128 + ((c ^ (row & 7)) * 16));
            size_t g = (size_t)(kt * 64 + row) * D + c * 8;
            cp_async16(base + so,        kg + g);
            cp_async16(base + 8192 + so, vg + g);
        }
        cp_commit();
    };

    auto load_bm = [&](int kt) {
        #pragma unroll
        for (int i = 0; i < 8; i++) {
            int id = t + i * 128;
            int row = id >> 4, c = id & 15;
            cp_async16(sb + AOFF_BIAS + (uint32_t)(row * 272 + c * 16),
                       biasbase + (size_t)row * SEQ + kt * 64 + c * 4);
        }
        #pragma unroll
        for (int i = 0; i < 2; i++) {
            int id = t + i * 128;
            int row = id >> 2, c = id & 3;
            cp_async16(sb + AOFF_MASK + (uint32_t)(row * 80 + c * 16),
                       maskbase + (size_t)row * SEQ + kt * 64 + c * 16);
        }
        cp_commit();
    };

    load_kv(0);
    load_bm(0);
    load_kv(1);

    float accO[8][4];
    #pragma unroll
    for (int j = 0; j < 8; j++)
        #pragma unroll
        for (int c = 0; c < 4; c++) accO[j][c] = 0.f;
    float m[2] = {-1e30f, -1e30f}, lsum[2] = {0.f, 0.f};

    const int NKT = SEQ / 64;
    for (int kt = 0; kt < NKT; kt++) {
        if (kt < NKT - 1) cp_wait1(); else cp_wait0();
        __syncthreads();

        uint32_t base = sb + AOFF_KV + (uint32_t)((kt & 1) * 16384);

        // ---- S = Q @ K^T  (Q pre-scaled; S in log2 domain) ----
        float s[8][4];
        #pragma unroll
        for (int j = 0; j < 8; j++)
            #pragma unroll
            for (int c = 0; c < 4; c++) s[j][c] = 0.f;

        #pragma unroll
        for (int kk = 0; kk < 4; kk++) {
            uint32_t qa[4];
            {
                int row = w * 16 + (lane & 15);
                int ch = kk * 2 + (lane >> 4);
                uint32_t so = (uint32_t)(row * 128 + ((ch ^ (row & 7)) * 16));
                ldsm_x4(sb + AOFF_Q + so, qa);
            }
            uint32_t kb[4][4];
            #pragma unroll
            for (int np = 0; np < 4; np++) {
                int row = np * 16 + (lane & 7) + ((lane & 16) ? 8 : 0);
                int ch = kk * 2 + ((lane >> 3) & 1);
                uint32_t so = (uint32_t)(row * 128 + ((ch ^ (row & 7)) * 16));
                ldsm_x4(base + so, kb[np]);
            }
            #pragma unroll
            for (int j = 0; j < 8; j++)
                mma_f16(s[j], qa, kb[j >> 1][(j & 1) * 2], kb[j >> 1][(j & 1) * 2 + 1]);
        }

        // ---- softmax in log2 domain ----
        #pragma unroll
        for (int hh = 0; hh < 2; hh++) {
            int row = w * 16 + (lane >> 2) + hh * 8;
            const float* bsm = (const float*)(smem + AOFF_BIAS + (size_t)row * 272)
                               + (lane & 3) * 2;
            const unsigned char* msm = (const unsigned char*)(smem + AOFF_MASK
                               + (size_t)row * 80) + (lane & 3) * 2;
            float mx = -1e30f;
            #pragma unroll
            for (int j = 0; j < 8; j++) {
                float2 bb = *(const float2*)(bsm + j * 8);
                uchar2 mm = *(const uchar2*)(msm + j * 8);
                float v0 = mm.x ? fmaf(bb.x, QSCALE, s[j][hh*2+0]) : -1e30f;
                float v1 = mm.y ? fmaf(bb.y, QSCALE, s[j][hh*2+1]) : -1e30f;
                s[j][hh*2+0] = v0; s[j][hh*2+1] = v1;
                mx = fmaxf(mx, fmaxf(v0, v1));
            }
            mx = fmaxf(mx, __shfl_xor_sync(0xffffffffu, mx, 1));
            mx = fmaxf(mx, __shfl_xor_sync(0xffffffffu, mx, 2));
            float mn = fmaxf(m[hh], mx);
            float alpha = exp2f(m[hh] - mn);
            m[hh] = mn;
            float rs = 0.f;
            #pragma unroll
            for (int j = 0; j < 8; j++) {
                float e0 = exp2f(s[j][hh*2+0] - mn);
                float e1 = exp2f(s[j][hh*2+1] - mn);
                s[j][hh*2+0] = e0; s[j][hh*2+1] = e1;
                rs += e0 + e1;
            }
            rs += __shfl_xor_sync(0xffffffffu, rs, 1);
            rs += __shfl_xor_sync(0xffffffffu, rs, 2);
            lsum[hh] = lsum[hh] * alpha + rs;
            #pragma unroll
            for (int j = 0; j < 8; j++) {
                accO[j][hh*2+0] *= alpha;
                accO[j][hh*2+1] *= alpha;
            }
        }

        // ---- O += P @ V ----
        #pragma unroll
        for (int kk = 0; kk < 4; kk++) {
            int j0 = kk * 2, j1 = kk * 2 + 1;
            uint32_t pa[4];
            pa[0] = pack_half2(s[j0][0], s[j0][1]);
            pa[1] = pack_half2(s[j0][2], s[j0][3]);
            pa[2] = pack_half2(s[j1][0], s[j1][1]);
            pa[3] = pack_half2(s[j1][2], s[j1][3]);
            uint32_t vb[4][4];
            #pragma unroll
            for (int np = 0; np < 4; np++) {
                int i = lane >> 3, jj = lane & 7;
                int tok = kk * 16 + (i & 1) * 8 + jj;
                int ch = np * 2 + (i >> 1);
                uint32_t so = (uint32_t)(tok * 128 + ((ch ^ (tok & 7)) * 16));
                ldsm_x4t(base + 8192 + so, vb[np]);
            }
            #pragma unroll
            for (int j = 0; j < 8; j++)
                mma_f16(accO[j], pa, vb[j >> 1][(j & 1) * 2], vb[j >> 1][(j & 1) * 2 + 1]);
        }
        __syncthreads();

        if (kt + 1 < NKT) load_bm(kt + 1);
        if (kt + 2 < NKT) load_kv(kt + 2);
    }

    // ---- epilogue: normalize + fp16 write ----
    #pragma unroll
    for (int hh = 0; hh < 2; hh++) {
        float inv = 1.0f / lsum[hh];
        size_t row = qrow0 + w * 16 + (lane >> 2) + hh * 8;
        #pragma unroll
        for (int j = 0; j < 8; j++) {
            int col = hd * HDIM + j * 8 + (lane & 3) * 2;
            *(uint32_t*)(out16 + row * D + col) =
                pack_half2(accO[j][hh*2+0] * inv, accO[j][hh*2+1] * inv);
        }
    }
}

// ---------------- host launcher --------------------------------------------------
extern "C" void kernel_launch(void* const* d_in, const int* in_sizes, int n_in,
                              void* d_out, int out_size) {
    const float* x     = (const float*)d_in[0];
    const float* bias  = (const float*)d_in[1];
    const int*   mask  = (const int*)d_in[2];
    const float* ln1_w = (const float*)d_in[3];
    const float* ln1_b = (const float*)d_in[4];
    const float* wq    = (const float*)d_in[5];
    const float* bq    = (const float*)d_in[6];
    const float* wk    = (const float*)d_in[7];
    const float* bk    = (const float*)d_in[8];
    const float* wv    = (const float*)d_in[9];
    const float* bv    = (const float*)d_in[10];
    const float* wo    = (const float*)d_in[11];
    const float* bo    = (const float*)d_in[12];
    const float* ln2_w = (const float*)d_in[13];
    const float* ln2_b = (const float*)d_in[14];
    const float* w1    = (const float*)d_in[15];
    const float* b1    = (const float*)d_in[16];
    const float* w2    = (const float*)d_in[17];
    const float* b2    = (const float*)d_in[18];
    float* out = (float*)d_out;

    float *xmid;
    __half *xn16, *q16, *k16, *v16, *a16, *h16, *wt16;
    unsigned char* mask8;
    cudaGetSymbolAddress((void**)&xmid, g_xmid);
    cudaGetSymbolAddress((void**)&xn16, g_xn16);
    cudaGetSymbolAddress((void**)&q16,  g_q16);
    cudaGetSymbolAddress((void**)&k16,  g_k16);
    cudaGetSymbolAddress((void**)&v16,  g_v16);
    cudaGetSymbolAddress((void**)&a16,  g_a16);
    cudaGetSymbolAddress((void**)&h16,  g_h16);
    cudaGetSymbolAddress((void**)&wt16, g_wt16);
    cudaGetSymbolAddress((void**)&mask8, g_mask8);

    cudaFuncSetAttribute(hmma_gemm, cudaFuncAttributeMaxDynamicSharedMemorySize, GSMEM_B);
    cudaFuncSetAttribute(qkv_gemm,  cudaFuncAttributeMaxDynamicSharedMemorySize, GSMEM_A);
    cudaFuncSetAttribute(attn_mma,  cudaFuncAttributeMaxDynamicSharedMemorySize, ASMEM);

    dim3 tgrid(24, 24, 6), tblk(32, 8);
    transpose6<<<tgrid, tblk>>>(wq, wk, wv, wo, w1, w2, wt16);
    mask_pack<<<(BATCH*SEQ*SEQ/4 + 255)/256, 256>>>(mask, mask8, BATCH*SEQ*SEQ/4);

    dim3 ggrid(D / 64, NROWS / 128);     // (12, 32) = 384
    dim3 qgrid(18, NROWS / 128);         // (18, 32) = 576

    // LN1 -> fp16
    ln_f16<<<NROWS, 256>>>(x, ln1_w, ln1_b, xn16);
    // merged QKV projections (128x128 tiles, BK=64; Q pre-scaled)
    qkv_gemm<<<qgrid, 256, GSMEM_A>>>(xn16, wt16, bq, bk, bv, q16, k16, v16);
    // attention: 64q tiles, 4 warps, 3 CTAs/SM
    dim3 attn_grid(SEQ / 64, NHEADS * BATCH);  // (32, 24) = 768
    attn_mma<<<attn_grid, 128, ASMEM>>>(q16, k16, v16, bias, mask8, a16);
    // out-proj + residual(x) -> xmid (fp32)  (128x64, BK=64, 3 CTAs/SM)
    hmma_gemm<<<ggrid, 256, GSMEM_B>>>(a16, wt16 + 3*(size_t)D*D, bo, x, xmid, nullptr, 0);
    // LN2 -> fp16
    ln_f16<<<NROWS, 256>>>(xmid, ln2_w, ln2_b, xn16);
    // MLP up + ReLU -> fp16 hidden
    hmma_gemm<<<ggrid, 256, GSMEM_B>>>(xn16, wt16 + 4*(size_t)D*D, b1, nullptr,
                                       nullptr, h16, 1);
    // MLP down + residual(xmid) -> out (fp32)
    hmma_gemm<<<ggrid, 256, GSMEM_B>>>(h16, wt16 + 5*(size_t)D*D, b2, xmid,
                                       out, nullptr, 0);
}